// round 3
// baseline (speedup 1.0000x reference)
#include <cuda_runtime.h>
#include <cstddef>

#define NW    100000
#define VD    128
#define BATCH 16384
#define KNUM  26
#define BLK   (KNUM * 32)   // 832 threads = 26 warps, one warp per k

// 51.2 MB transposed copy of O: OT[word][v]. Static device scratch (no alloc).
__device__ float g_OT[(size_t)NW * VD];

// ---------------------------------------------------------------------------
// Kernel 1: transpose O [VD, NW] -> OT [NW, VD], tiled 32x32 via smem.
// Grid: (NW/32, VD/32) = (3125, 4). Block: (32, 8). DRAM-bound.
// ---------------------------------------------------------------------------
__global__ void transpose_kernel(const float* __restrict__ O) {
    __shared__ float tile[32][33];  // +1 pad: conflict-free transpose read
    const int w0 = blockIdx.x * 32;
    const int v0 = blockIdx.y * 32;
    const int tx = threadIdx.x;
    const int ty = threadIdx.y;

#pragma unroll
    for (int j = 0; j < 32; j += 8) {
        tile[ty + j][tx] = O[(size_t)(v0 + ty + j) * NW + (w0 + tx)];
    }
    __syncthreads();
#pragma unroll
    for (int j = 0; j < 32; j += 8) {
        g_OT[(size_t)(w0 + ty + j) * VD + (v0 + tx)] = tile[tx][ty + j];
    }
}

// ---------------------------------------------------------------------------
// Kernel 2: one block (26 warps) per batch element; warp wid owns k = wid.
// Single short dependency chain per warp, no loops, no smem, no barriers.
// D row is read by all 26 warps of the CTA: first warp misses, rest are
// L1 hits (same SM). OT row read is one coalesced LDG.128 x 32 lanes.
// ---------------------------------------------------------------------------
__global__ __launch_bounds__(BLK, 2)
void score_kernel(const int* __restrict__ doc_ids,
                  const int* __restrict__ tnids,
                  const float* __restrict__ D,
                  float* __restrict__ out) {
    const int b    = blockIdx.x;
    const int t    = threadIdx.x;
    const int lane = t & 31;
    const int k    = t >> 5;          // warp id == k, 0..25

    const int doc  = __ldg(&doc_ids[b]);
    const int word = __ldg(&tnids[b * KNUM + k]);

    const float4 dv =
        __ldg(reinterpret_cast<const float4*>(D + (size_t)doc * VD) + lane);
    const float4 w4 =
        *(reinterpret_cast<const float4*>(g_OT + (size_t)word * VD) + lane);

    float s = dv.x * w4.x + dv.y * w4.y + dv.z * w4.z + dv.w * w4.w;
    s += __shfl_xor_sync(0xffffffffu, s, 16);
    s += __shfl_xor_sync(0xffffffffu, s, 8);
    s += __shfl_xor_sync(0xffffffffu, s, 4);
    s += __shfl_xor_sync(0xffffffffu, s, 2);
    s += __shfl_xor_sync(0xffffffffu, s, 1);
    if (lane == 0) out[b * KNUM + k] = s;
}

// ---------------------------------------------------------------------------
// Inputs (metadata order): context_ids[B] i32 (unused), doc_ids[B] i32,
// target_noise_ids[B*K] i32, D[NUM_DOCS*VD] f32, O[VD*NW] f32.
// Output: out[B*K] f32.
// ---------------------------------------------------------------------------
extern "C" void kernel_launch(void* const* d_in, const int* in_sizes, int n_in,
                              void* d_out, int out_size) {
    const int*   doc_ids = (const int*)d_in[1];
    const int*   tnids   = (const int*)d_in[2];
    const float* D       = (const float*)d_in[3];
    const float* O       = (const float*)d_in[4];
    float*       out     = (float*)d_out;

    dim3 tg(NW / 32, VD / 32);
    dim3 tb(32, 8);
    transpose_kernel<<<tg, tb>>>(O);

    score_kernel<<<BATCH, BLK>>>(doc_ids, tnids, D, out);
}

// round 4
// speedup vs baseline: 2.2092x; 2.2092x over previous
#include <cuda_runtime.h>
#include <cstddef>

#define NW    100000
#define VD    128
#define BATCH 16384
#define KNUM  26
#define NSLOT 7   // max k-slots per warp (wid + 4*i)

// 51.2 MB transposed copy of O: OT[word][v]. Static device scratch (no alloc).
__device__ float g_OT[(size_t)NW * VD];

// ---------------------------------------------------------------------------
// Kernel 1: transpose O [VD, NW] -> OT [NW, VD], tiled 32x32 via smem.
// Reads: scalar, coalesced along w. Writes: float4 (STG.128) along v.
// Grid: (NW/32, VD/32) = (3125, 4). Block: 256.
// ---------------------------------------------------------------------------
__global__ void transpose_kernel(const float* __restrict__ O) {
    __shared__ float tile[32][33];  // +1 pad
    const int w0 = blockIdx.x * 32;
    const int v0 = blockIdx.y * 32;
    const int t  = threadIdx.x;
    const int tx = t & 31;          // w_local for read phase
    const int ty = t >> 5;          // v_local base for read phase

#pragma unroll
    for (int j = 0; j < 32; j += 8) {
        tile[ty + j][tx] = O[(size_t)(v0 + ty + j) * NW + (w0 + tx)];
    }
    __syncthreads();

    // write phase: 256 threads = 32 w_local x 8 v-chunks of float4
    const int wl = t >> 3;          // 0..31
    const int vc = t & 7;           // 0..7
    float4 o;
    o.x = tile[4 * vc + 0][wl];
    o.y = tile[4 * vc + 1][wl];
    o.z = tile[4 * vc + 2][wl];
    o.w = tile[4 * vc + 3][wl];
    *reinterpret_cast<float4*>(g_OT + (size_t)(w0 + wl) * VD + v0 + 4 * vc) = o;
}

// ---------------------------------------------------------------------------
// Kernel 2: one block (128 threads = 4 warps) per batch element b.
// Warp wid owns k = wid, wid+4, ... Software-pipelined: prefetch next OT row
// (one LDG.128) before the dot+shuffle reduction of the current row, so the
// ~250cyc L2 hit overlaps the ~150cyc reduce chain. Regs target <= 32.
// ---------------------------------------------------------------------------
__global__ __launch_bounds__(VD)
void score_kernel(const int* __restrict__ doc_ids,
                  const int* __restrict__ tnids,
                  const float* __restrict__ D,
                  float* __restrict__ out) {
    const int b    = blockIdx.x;
    const int t    = threadIdx.x;
    const int lane = t & 31;
    const int wid  = t >> 5;

    __shared__ __align__(16) float sd[VD];
    __shared__ int swords[KNUM];

    const int doc = __ldg(&doc_ids[b]);
    sd[t] = D[(size_t)doc * VD + t];
    if (t < KNUM) swords[t] = __ldg(&tnids[b * KNUM + t]);
    __syncthreads();

    const float4 dv = reinterpret_cast<const float4*>(sd)[lane];

    // prologue: load row for k = wid
    float4 cur = *(reinterpret_cast<const float4*>(
                       g_OT + (size_t)swords[wid] * VD) + lane);

#pragma unroll
    for (int i = 0; i < NSLOT; i++) {
        const int k  = wid + 4 * i;
        const int kn = k + 4;

        // prefetch next row before reducing current
        float4 nxt;
        if (kn < KNUM) {
            nxt = *(reinterpret_cast<const float4*>(
                        g_OT + (size_t)swords[kn] * VD) + lane);
        }

        if (k < KNUM) {
            float s = dv.x * cur.x + dv.y * cur.y +
                      dv.z * cur.z + dv.w * cur.w;
            s += __shfl_xor_sync(0xffffffffu, s, 16);
            s += __shfl_xor_sync(0xffffffffu, s, 8);
            s += __shfl_xor_sync(0xffffffffu, s, 4);
            s += __shfl_xor_sync(0xffffffffu, s, 2);
            s += __shfl_xor_sync(0xffffffffu, s, 1);
            if (lane == 0) out[b * KNUM + k] = s;
        }
        cur = nxt;
    }
}

// ---------------------------------------------------------------------------
// Inputs (metadata order): context_ids[B] i32 (unused), doc_ids[B] i32,
// target_noise_ids[B*K] i32, D[NUM_DOCS*VD] f32, O[VD*NW] f32.
// Output: out[B*K] f32.
// ---------------------------------------------------------------------------
extern "C" void kernel_launch(void* const* d_in, const int* in_sizes, int n_in,
                              void* d_out, int out_size) {
    const int*   doc_ids = (const int*)d_in[1];
    const int*   tnids   = (const int*)d_in[2];
    const float* D       = (const float*)d_in[3];
    const float* O       = (const float*)d_in[4];
    float*       out     = (float*)d_out;

    dim3 tg(NW / 32, VD / 32);
    transpose_kernel<<<tg, 256>>>(O);

    score_kernel<<<BATCH, VD>>>(doc_ids, tnids, D, out);
}